// round 2
// baseline (speedup 1.0000x reference)
#include <cuda_runtime.h>

// AffinityLoss: loss = mean_b,i,j |softmax_b(G1)[b,i,j] - softmax_b(G2)[b,i,j]|
// averaged over 2 levels. G[b,i,j] = sum_c f[b,c,i] f[b,c,j] (never materialized).
// Fused tiled kernel: each CTA computes 8 gram tiles (2 tensors x 4 batches) for
// one (i,j) 64x64 tile, does the 4-entry batch softmax + |diff| in registers,
// block-reduces, atomicAdds into a device double accumulator.
// Symmetry in (i,j): only upper-triangular tiles computed (off-diag weight 2).
// Inner product uses packed fma.rn.f32x2 (FFMA2) for 2x fp32 FMA throughput.

#define NG 8        // 2 tensors * 4 batches
#define KC 32       // K chunk
#define TI 64
#define TJ 64
#define NTHREADS 256

__device__ double g_accum[2];

__global__ void zero_accum_kernel() {
    g_accum[0] = 0.0;
    g_accum[1] = 0.0;
}

__device__ __forceinline__ unsigned long long pack_dup(float x) {
    unsigned long long r;
    unsigned int u = __float_as_uint(x);
    asm("mov.b64 %0, {%1, %1};" : "=l"(r) : "r"(u));
    return r;
}

__device__ __forceinline__ void fma2(unsigned long long& acc,
                                     unsigned long long a,
                                     unsigned long long b) {
    asm("fma.rn.f32x2 %0, %1, %2, %0;" : "+l"(acc) : "l"(a), "l"(b));
}

__device__ __forceinline__ void unpack2(unsigned long long v, float& lo, float& hi) {
    unsigned int l, h;
    asm("mov.b64 {%0, %1}, %2;" : "=r"(l), "=r"(h) : "l"(v));
    lo = __uint_as_float(l);
    hi = __uint_as_float(h);
}

// softmax over 4 batch entries for both tensors, sum of abs diffs
__device__ __forceinline__ float pair_loss(const float* ga, const float* gb) {
    float m1 = fmaxf(fmaxf(ga[0], ga[1]), fmaxf(ga[2], ga[3]));
    float m2 = fmaxf(fmaxf(gb[0], gb[1]), fmaxf(gb[2], gb[3]));
    float e1[4], e2[4];
    float s1 = 0.f, s2 = 0.f;
#pragma unroll
    for (int b = 0; b < 4; b++) { e1[b] = __expf(ga[b] - m1); s1 += e1[b]; }
#pragma unroll
    for (int b = 0; b < 4; b++) { e2[b] = __expf(gb[b] - m2); s2 += e2[b]; }
    float r1 = 1.0f / s1, r2 = 1.0f / s2;
    float d = 0.f;
#pragma unroll
    for (int b = 0; b < 4; b++) d += fabsf(e1[b] * r1 - e2[b] * r2);
    return d;
}

template <int C, int HW>
__global__ __launch_bounds__(NTHREADS, 1)
void affinity_loss_kernel(const float* __restrict__ f1,
                          const float* __restrict__ f2,
                          int slot) {
    static_assert(TI == 64 && TJ == 64 && KC == 32, "index math assumes 64/64/32");
    extern __shared__ float smem[];
    float* As = smem;                  // [NG][KC][TI]
    float* Bs = smem + NG * KC * TI;   // [NG][KC][TJ]

    const int tid = threadIdx.x;

    // map linear block id -> upper-triangular tile (I, J), I <= J
    const int T = HW / TI;
    int I = 0, rem = (int)blockIdx.x;
    while (rem >= T - I) { rem -= T - I; I++; }
    const int J = I + rem;
    const int i0 = I * TI, j0 = J * TJ;
    const float w = (I == J) ? 1.0f : 2.0f;

    const int tx = tid & 15;   // 16 j-positions (4 floats = 2 f32x2 pairs each)
    const int ty = tid >> 4;   // 16 i-positions (4 floats each)

    unsigned long long acc[NG][4][2];
#pragma unroll
    for (int g = 0; g < NG; g++)
#pragma unroll
        for (int ii = 0; ii < 4; ii++) {
            acc[g][ii][0] = 0ULL;
            acc[g][ii][1] = 0ULL;
        }

    const float* fptr[2] = { f1, f2 };

    for (int kc = 0; kc < C; kc += KC) {
        // cooperative load: NG*KC*(TI/4) = 4096 float4 per side, 16 per thread
#pragma unroll
        for (int it = 0; it < (NG * KC * (TI / 4)) / NTHREADS; it++) {
            int idx = it * NTHREADS + tid;
            int i4 = idx & 15;             // float4 index within row
            int k  = (idx >> 4) & (KC - 1);
            int g  = idx >> 9;             // / (16*32)
            int t = g >> 2, b = g & 3;
            const float* base = fptr[t] + (b * C + kc + k) * HW;
            reinterpret_cast<float4*>(As)[idx] =
                reinterpret_cast<const float4*>(base + i0)[i4];
            reinterpret_cast<float4*>(Bs)[idx] =
                reinterpret_cast<const float4*>(base + j0)[i4];
        }
        __syncthreads();

#pragma unroll 2
        for (int k = 0; k < KC; k++) {
#pragma unroll
            for (int g = 0; g < NG; g++) {
                const float4 av =
                    *reinterpret_cast<const float4*>(As + (g * KC + k) * TI + ty * 4);
                const ulonglong2 bv =
                    *reinterpret_cast<const ulonglong2*>(Bs + (g * KC + k) * TJ + tx * 4);
                unsigned long long a0 = pack_dup(av.x);
                unsigned long long a1 = pack_dup(av.y);
                unsigned long long a2 = pack_dup(av.z);
                unsigned long long a3 = pack_dup(av.w);
                fma2(acc[g][0][0], a0, bv.x); fma2(acc[g][0][1], a0, bv.y);
                fma2(acc[g][1][0], a1, bv.x); fma2(acc[g][1][1], a1, bv.y);
                fma2(acc[g][2][0], a2, bv.x); fma2(acc[g][2][1], a2, bv.y);
                fma2(acc[g][3][0], a3, bv.x); fma2(acc[g][3][1], a3, bv.y);
            }
        }
        __syncthreads();
    }

    // epilogue: batch softmax + abs diff per output element
    float local = 0.f;
#pragma unroll
    for (int ii = 0; ii < 4; ii++) {
#pragma unroll
        for (int jp = 0; jp < 2; jp++) {
            float g1lo[4], g1hi[4], g2lo[4], g2hi[4];
#pragma unroll
            for (int b = 0; b < 4; b++) {
                unpack2(acc[b][ii][jp],     g1lo[b], g1hi[b]);
                unpack2(acc[4 + b][ii][jp], g2lo[b], g2hi[b]);
            }
            local += pair_loss(g1lo, g2lo);
            local += pair_loss(g1hi, g2hi);
        }
    }
    local *= w;

    // block reduction
#pragma unroll
    for (int off = 16; off > 0; off >>= 1)
        local += __shfl_xor_sync(0xffffffffu, local, off);
    __shared__ float red[NTHREADS / 32];
    if ((tid & 31) == 0) red[tid >> 5] = local;
    __syncthreads();
    if (tid == 0) {
        float s = 0.f;
#pragma unroll
        for (int i = 0; i < NTHREADS / 32; i++) s += red[i];
        atomicAdd(&g_accum[slot], (double)s);
    }
}

__global__ void finalize_kernel(float* out) {
    const double n0 = 4.0 * 4096.0 * 4096.0;
    const double n1 = 4.0 * 1024.0 * 1024.0;
    out[0] = (float)(0.5 * (g_accum[0] / n0 + g_accum[1] / n1));
}

extern "C" void kernel_launch(void* const* d_in, const int* in_sizes, int n_in,
                              void* d_out, int out_size) {
    const float* f10 = (const float*)d_in[0];  // fea1_0 [4,64,64,64]
    const float* f11 = (const float*)d_in[1];  // fea1_1 [4,128,32,32]
    const float* f20 = (const float*)d_in[2];  // fea2_0 [4,64,64,64]
    const float* f21 = (const float*)d_in[3];  // fea2_1 [4,128,32,32]
    float* out = (float*)d_out;

    const size_t smem = (size_t)NG * KC * (TI + TJ) * sizeof(float); // 128 KB
    cudaFuncSetAttribute(affinity_loss_kernel<64, 4096>,
                         cudaFuncAttributeMaxDynamicSharedMemorySize, (int)smem);
    cudaFuncSetAttribute(affinity_loss_kernel<128, 1024>,
                         cudaFuncAttributeMaxDynamicSharedMemorySize, (int)smem);

    zero_accum_kernel<<<1, 1>>>();

    const int T0 = 4096 / TI;                 // 64
    const int nb0 = T0 * (T0 + 1) / 2;        // 2080
    affinity_loss_kernel<64, 4096><<<nb0, NTHREADS, smem>>>(f10, f20, 0);

    const int T1 = 1024 / TI;                 // 16
    const int nb1 = T1 * (T1 + 1) / 2;        // 136
    affinity_loss_kernel<128, 1024><<<nb1, NTHREADS, smem>>>(f11, f21, 1);

    finalize_kernel<<<1, 1>>>(out);
}

// round 15
// speedup vs baseline: 1.8581x; 1.8581x over previous
#include <cuda_runtime.h>
#include <cstdint>

// AffinityLoss via warp-level mma.sync tf32 (sm_80-era PTX; the harness builds
// at plain sm_103, so tcgen05 ('a'-features) are unavailable — measured R7).
// G_g[i,j] = sum_c f_g[c,i] f_g[c,j] for 8 groups (2 tensors x 4 batches).
// Upper-triangular 64x64 (i,j) tiles, tile weight 1 (diag) / 2 (off-diag);
// diagonal tiles count all ordered pairs once, off-diag tiles stand for both
// (I,J) and (J,I) -> exact full ordered sum (verified structure from R2).
// Inputs pre-rounded to tf32 by a prep kernel so the hot loop has no cvts.

#define NG 8
#define TI 64
#define TJ 64
#define KC 32
#define NTHREADS 256
#define AROW 72                      // SMEM row stride in floats (64 + 8 pad)
#define GSTRIDE (KC * AROW)          // words per group tile (2304)
#define BS_OFF (NG * GSTRIDE)        // B side offset in words (18432)
#define SMEM_WORDS (2 * NG * GSTRIDE)
#define SMEM_BYTES (SMEM_WORDS * 4)  // 147456

__device__ double g_accum[2];
__device__ float g_c0[2][4 * 64 * 4096];   // tf32-rounded level0 [tensor][b*c*hw]
__device__ float g_c1[2][4 * 128 * 1024];  // tf32-rounded level1

__global__ void zero_accum_kernel() { g_accum[0] = 0.0; g_accum[1] = 0.0; }

__device__ __forceinline__ uint32_t to_tf32(float v) {
    uint32_t o;
    asm("cvt.rna.tf32.f32 %0, %1;" : "=r"(o) : "f"(v));
    return o;
}

template <int LEVEL, int TSEL, int N4>
__global__ void convert_kernel(const float* __restrict__ f) {
    float* out = (LEVEL == 0) ? g_c0[TSEL] : g_c1[TSEL];
    int idx = blockIdx.x * blockDim.x + threadIdx.x;
    for (int i = idx; i < N4; i += gridDim.x * blockDim.x) {
        float4 v = reinterpret_cast<const float4*>(f)[i];
        uint4 o;
        o.x = to_tf32(v.x); o.y = to_tf32(v.y);
        o.z = to_tf32(v.z); o.w = to_tf32(v.w);
        reinterpret_cast<uint4*>(out)[i] = o;
    }
}

__device__ __forceinline__ void mma_tf32(float* c,
                                         uint32_t a0, uint32_t a1, uint32_t a2, uint32_t a3,
                                         uint32_t b0, uint32_t b1) {
    asm volatile(
        "mma.sync.aligned.m16n8k8.row.col.f32.tf32.tf32.f32 "
        "{%0,%1,%2,%3}, {%4,%5,%6,%7}, {%8,%9}, {%0,%1,%2,%3};"
        : "+f"(c[0]), "+f"(c[1]), "+f"(c[2]), "+f"(c[3])
        : "r"(a0), "r"(a1), "r"(a2), "r"(a3), "r"(b0), "r"(b1));
}

// softmax over 4 batches for both tensors, sum |diff|
__device__ __forceinline__ float pair_loss(const float* ga, const float* gb) {
    float m1 = fmaxf(fmaxf(ga[0], ga[1]), fmaxf(ga[2], ga[3]));
    float m2 = fmaxf(fmaxf(gb[0], gb[1]), fmaxf(gb[2], gb[3]));
    float e1[4], e2[4], s1 = 0.f, s2 = 0.f;
#pragma unroll
    for (int b = 0; b < 4; b++) { e1[b] = __expf(ga[b] - m1); s1 += e1[b]; }
#pragma unroll
    for (int b = 0; b < 4; b++) { e2[b] = __expf(gb[b] - m2); s2 += e2[b]; }
    float r1 = 1.0f / s1, r2 = 1.0f / s2, d = 0.f;
#pragma unroll
    for (int b = 0; b < 4; b++) d += fabsf(e1[b] * r1 - e2[b] * r2);
    return d;
}

template <int C, int HW, int LEVEL>
__global__ __launch_bounds__(NTHREADS, 1)
void affinity_mma_kernel(int slot) {
    extern __shared__ float smem[];   // [A: NG*GSTRIDE][B: NG*GSTRIDE]
    const int tid = threadIdx.x;
    const int wid = tid >> 5, lane = tid & 31;
    const int lk = lane & 3;          // k within 4
    const int lr = lane >> 2;         // row/col within 8
    const int wi = wid >> 2;          // warp i block (0-1): 32 rows
    const int wj = wid & 3;           // warp j block (0-3): 16 cols

    // upper-triangular 64x64 tile map: I <= J
    const int T = HW / TI;
    int I = 0, rem = (int)blockIdx.x;
    while (rem >= T - I) { rem -= T - I; I++; }
    const int J = I + rem;
    const int i0 = I * TI, j0 = J * TJ;
    const float w = (I == J) ? 1.0f : 2.0f;

    const float* fc[2];
    if (LEVEL == 0) { fc[0] = g_c0[0]; fc[1] = g_c0[1]; }
    else            { fc[0] = g_c1[0]; fc[1] = g_c1[1]; }

    float acc[NG][2][2][4];           // [group][mt][nt][frag]
#pragma unroll
    for (int g = 0; g < NG; g++)
#pragma unroll
        for (int mt = 0; mt < 2; mt++)
#pragma unroll
            for (int nt = 0; nt < 2; nt++)
#pragma unroll
                for (int q = 0; q < 4; q++) acc[g][mt][nt][q] = 0.f;

    const int NCHUNK = C / KC;
    for (int ch = 0; ch < NCHUNK; ch++) {
        const int kc0 = ch * KC;
        if (ch > 0) __syncthreads();
        // fill A and B tiles: [g][k][i] rows padded to AROW floats
#pragma unroll
        for (int it = 0; it < (NG * KC * (TI / 4)) / NTHREADS; it++) {
            int idx = it * NTHREADS + tid;        // [0, 4096)
            int i4 = idx & 15;
            int k  = (idx >> 4) & (KC - 1);
            int g  = idx >> 9;
            int t = g >> 2, b = g & 3;
            const float* src = fc[t] + (b * C + kc0 + k) * HW;
            int dst = g * GSTRIDE + k * AROW + i4 * 4;
            *reinterpret_cast<float4*>(smem + dst) =
                *reinterpret_cast<const float4*>(src + i0 + i4 * 4);
            *reinterpret_cast<float4*>(smem + BS_OFF + dst) =
                *reinterpret_cast<const float4*>(src + j0 + i4 * 4);
        }
        __syncthreads();

#pragma unroll
        for (int ks = 0; ks < KC / 8; ks++) {
#pragma unroll
            for (int g = 0; g < NG; g++) {
                const float* Ag  = smem + g * GSTRIDE + (ks * 8 + lk) * AROW;
                const float* Ag4 = Ag + 4 * AROW;
                const float* Bg  = smem + BS_OFF + g * GSTRIDE + (ks * 8 + lk) * AROW;
                const float* Bg4 = Bg + 4 * AROW;
                uint32_t a[2][4], bfr[2][2];
#pragma unroll
                for (int mt = 0; mt < 2; mt++) {
                    int r = wi * 32 + mt * 16 + lr;
                    a[mt][0] = __float_as_uint(Ag[r]);
                    a[mt][1] = __float_as_uint(Ag[r + 8]);
                    a[mt][2] = __float_as_uint(Ag4[r]);
                    a[mt][3] = __float_as_uint(Ag4[r + 8]);
                }
#pragma unroll
                for (int nt = 0; nt < 2; nt++) {
                    int n = wj * 16 + nt * 8 + lr;
                    bfr[nt][0] = __float_as_uint(Bg[n]);
                    bfr[nt][1] = __float_as_uint(Bg4[n]);
                }
#pragma unroll
                for (int mt = 0; mt < 2; mt++)
#pragma unroll
                    for (int nt = 0; nt < 2; nt++)
                        mma_tf32(acc[g][mt][nt],
                                 a[mt][0], a[mt][1], a[mt][2], a[mt][3],
                                 bfr[nt][0], bfr[nt][1]);
            }
        }
    }

    // epilogue: every (mt,nt,frag) is a distinct (i,j) in the tile; tile weight
    float local = 0.f;
#pragma unroll
    for (int mt = 0; mt < 2; mt++)
#pragma unroll
        for (int nt = 0; nt < 2; nt++)
#pragma unroll
            for (int q = 0; q < 4; q++) {
                float ga[4], gb[4];
#pragma unroll
                for (int b = 0; b < 4; b++) {
                    ga[b] = acc[b][mt][nt][q];
                    gb[b] = acc[4 + b][mt][nt][q];
                }
                local += pair_loss(ga, gb);
            }
    local *= w;

#pragma unroll
    for (int off = 16; off > 0; off >>= 1)
        local += __shfl_xor_sync(0xffffffffu, local, off);
    __shared__ float red[NTHREADS / 32];
    if (lane == 0) red[wid] = local;
    __syncthreads();
    if (tid == 0) {
        float s = 0.f;
#pragma unroll
        for (int i = 0; i < NTHREADS / 32; i++) s += red[i];
        atomicAdd(&g_accum[slot], (double)s);
    }
}

__global__ void finalize_kernel(float* out) {
    const double n0 = 4.0 * 4096.0 * 4096.0;
    const double n1 = 4.0 * 1024.0 * 1024.0;
    out[0] = (float)(0.5 * (g_accum[0] / n0 + g_accum[1] / n1));
}

extern "C" void kernel_launch(void* const* d_in, const int* in_sizes, int n_in,
                              void* d_out, int out_size) {
    const float* f10 = (const float*)d_in[0];  // fea1_0 [4,64,64,64]
    const float* f11 = (const float*)d_in[1];  // fea1_1 [4,128,32,32]
    const float* f20 = (const float*)d_in[2];  // fea2_0 [4,64,64,64]
    const float* f21 = (const float*)d_in[3];  // fea2_1 [4,128,32,32]
    float* out = (float*)d_out;

    cudaFuncSetAttribute(affinity_mma_kernel<64, 4096, 0>,
                         cudaFuncAttributeMaxDynamicSharedMemorySize, SMEM_BYTES);
    cudaFuncSetAttribute(affinity_mma_kernel<128, 1024, 1>,
                         cudaFuncAttributeMaxDynamicSharedMemorySize, SMEM_BYTES);

    zero_accum_kernel<<<1, 1>>>();

    // pre-round inputs to tf32 (rna) so the gram loop needs no conversions
    constexpr int N40 = (4 * 64 * 4096) / 4;
    constexpr int N41 = (4 * 128 * 1024) / 4;
    convert_kernel<0, 0, N40><<<512, 256>>>(f10);
    convert_kernel<0, 1, N40><<<512, 256>>>(f20);
    convert_kernel<1, 0, N41><<<256, 256>>>(f11);
    convert_kernel<1, 1, N41><<<256, 256>>>(f21);

    // level 0: 64 tile-blocks -> 64*65/2 = 2080 CTAs
    affinity_mma_kernel<64, 4096, 0><<<2080, NTHREADS, SMEM_BYTES>>>(0);
    // level 1: 16 tile-blocks -> 16*17/2 = 136 CTAs
    affinity_mma_kernel<128, 1024, 1><<<136, NTHREADS, SMEM_BYTES>>>(1);

    finalize_kernel<<<1, 1>>>(out);
}